// round 14
// baseline (speedup 1.0000x reference)
#include <cuda_runtime.h>
#include <cuda_bf16.h>
#include <math.h>
#include <cstdint>

#define BATCH 4
#define HIMG 256
#define WIMG 256
#define CCH 128
#define TOK (BATCH*HIMG*WIMG)   // 262144
#define EPSV 1.001e-05f

// ---------------- scratch ----------------
__device__ __align__(16) __nv_bfloat16 g_att[ (size_t)TOK*CCH ];
__device__ __align__(16) float         g_y1 [ (size_t)TOK*CCH ];
__device__ __align__(16) __nv_bfloat16 g_h2 [ (size_t)TOK*CCH ];
__device__ __align__(16) __nv_bfloat16 g_m1 [ (size_t)TOK*4*CCH ];
__device__ __align__(16) __nv_bfloat16 g_wq [ 128*384 ];
__device__ __align__(16) __nv_bfloat16 g_wp [ 128*128 ];
__device__ __align__(16) __nv_bfloat16 g_w1b[ 128*512 ];
__device__ __align__(16) __nv_bfloat16 g_w2b[ 512*128 ];

// ---------------- helpers ----------------
__device__ __forceinline__ uint32_t smem_u32(const void* p) {
    uint32_t a;
    asm("{ .reg .u64 t; cvta.to.shared.u64 t, %1; cvt.u32.u64 %0, t; }" : "=r"(a) : "l"(p));
    return a;
}
__device__ __forceinline__ uint32_t pack_bf16(float lo, float hi) {
    uint32_t r;
    asm("cvt.rn.bf16x2.f32 %0, %1, %2;" : "=r"(r) : "f"(hi), "f"(lo));
    return r;
}
__device__ __forceinline__ void cp_async16(uint32_t dst, const void* src) {
    asm volatile("cp.async.cg.shared.global [%0], [%1], 16;" :: "r"(dst), "l"(src));
}
__device__ __forceinline__ void cp_commit() { asm volatile("cp.async.commit_group;"); }
template<int N>
__device__ __forceinline__ void cp_wait() { asm volatile("cp.async.wait_group %0;" :: "n"(N)); }

__device__ __forceinline__ void ldm_x4(uint32_t* r, uint32_t a) {
    asm volatile("ldmatrix.sync.aligned.m8n8.x4.shared.b16 {%0,%1,%2,%3}, [%4];"
        : "=r"(r[0]), "=r"(r[1]), "=r"(r[2]), "=r"(r[3]) : "r"(a));
}
__device__ __forceinline__ void ldm_x4_t(uint32_t* r, uint32_t a) {
    asm volatile("ldmatrix.sync.aligned.m8n8.x4.trans.shared.b16 {%0,%1,%2,%3}, [%4];"
        : "=r"(r[0]), "=r"(r[1]), "=r"(r[2]), "=r"(r[3]) : "r"(a));
}
__device__ __forceinline__ void mma16816(float* d, const uint32_t* a, uint32_t b0, uint32_t b1) {
    asm volatile("mma.sync.aligned.m16n8k16.row.col.f32.bf16.bf16.f32 "
        "{%0,%1,%2,%3}, {%4,%5,%6,%7}, {%8,%9}, {%0,%1,%2,%3};"
        : "+f"(d[0]), "+f"(d[1]), "+f"(d[2]), "+f"(d[3])
        : "r"(a[0]), "r"(a[1]), "r"(a[2]), "r"(a[3]), "r"(b0), "r"(b1));
}
// fast GELU: tanh form with HW tanh.approx (sm_75+). Deviation from exact-erf
// GELU is ~1e-5 abs in the |x|<1 range these activations live in; tanh.approx
// adds ~2^-11 rel — both far below the bf16 storage quantization of m1.
__device__ __forceinline__ float gelu_fast(float x) {
    float t = 0.79788456080286536f * (x + 0.044715f * x * x * x);
    float th;
    asm("tanh.approx.f32 %0, %1;" : "=f"(th) : "f"(t));
    return 0.5f * x * (1.0f + th);
}
// window-layout row -> image row (window reverse + unshift)
__device__ __forceinline__ size_t calc_orow(int row) {
    int win = row >> 6, r6 = row & 63;
    int bi = win >> 10, wim = win & 1023;
    int wh = wim >> 5, wc = wim & 31;
    int ii = r6 >> 3, jj = r6 & 7;
    int oh = (wh * 8 + ii + 4) & 255;
    int ow = (wc * 8 + jj + 4) & 255;
    return ((size_t)(bi * 256 + oh) * 256 + ow);
}

// ---------------- fp32 -> bf16 weight convert ----------------------------------
__global__ void convw_kernel(const float* __restrict__ w0, __nv_bfloat16* __restrict__ t0,
                             const float* __restrict__ w1, __nv_bfloat16* __restrict__ t1,
                             const float* __restrict__ w2, __nv_bfloat16* __restrict__ t2,
                             const float* __restrict__ w3, __nv_bfloat16* __restrict__ t3) {
    int i = blockIdx.x * 256 + threadIdx.x;
    const float* w; __nv_bfloat16* t; int base;
    if (i < 12288)      { w = w0; t = t0; base = 0; }
    else if (i < 16384) { w = w1; t = t1; base = 12288; }
    else if (i < 32768) { w = w2; t = t2; base = 16384; }
    else                { w = w3; t = t3; base = 32768; }
    int j = i - base;
    float4 v = ((const float4*)w)[j];
    uint2 p;
    p.x = pack_bf16(v.x, v.y);
    p.y = pack_bf16(v.z, v.w);
    *(uint2*)(t + (size_t)j * 4) = p;
}

// ---------------- fused LN1 + qkv GEMM + window attention ----------------------
#define FQ_AOFF 0
#define FQ_BOFF 32768
#define FQ_QOFF 49152       // doubles as fp32 x-staging (64KB over q+k) before GEMM
#define FQ_KOFF 81920
#define FQ_VOFF 114688
#define FQ_TOFF 147456
#define FQ_LOFF 151056
#define FQ_JOFF 151568
#define FQ_SMEM 151824

__global__ __launch_bounds__(256) void fused_qkv_attn(
    const float* __restrict__ x, const float* __restrict__ g1, const float* __restrict__ b1ln,
    const __nv_bfloat16* __restrict__ wq,
    const float* __restrict__ qkvb, const float* __restrict__ rpb,
    __nv_bfloat16* __restrict__ out)
{
    extern __shared__ char sm[];
    float* tbl  = (float*)(sm + FQ_TOFF);
    int*   lab  = (int*)(sm + FQ_LOFF);
    int*   joff = (int*)(sm + FQ_JOFF);

    const int tid  = threadIdx.x;
    const int lane = tid & 31;
    const int wid  = tid >> 5;
    const int wm   = wid & 3;
    const int wn   = wid >> 2;
    const int bm   = blockIdx.x * 128;

    const uint32_t s_base = smem_u32(sm);
    const uint32_t s_a = s_base + FQ_AOFF;
    const uint32_t s_b = s_base + FQ_BOFF;
    const uint32_t s_x = s_base + FQ_QOFF;   // fp32 staging, consumed before q is written

    // stage x rows (gathered via window reverse): 128 tokens x 512B
    #pragma unroll
    for (int u = 0; u < 16; u++) {
        int s = u * 256 + tid;          // 0..4095
        int lt = s >> 5, seg = s & 31;
        size_t orow = calc_orow(bm + lt);
        cp_async16(s_x + lt * 512 + seg * 16, x + orow * 128 + seg * 4);
    }
    cp_commit();

    auto load_b = [&](int t, int buf) {
        uint32_t bbase = s_b + buf * 8192;
        #pragma unroll
        for (int r2 = 0; r2 < 2; r2++) {
            int s = tid + r2 * 256;
            int row = s >> 4, seg = s & 15;
            cp_async16(bbase + row * 256 + ((seg ^ (row & 7)) << 4),
                       wq + (size_t)((t & 3) * 32 + row) * 384 + (t >> 2) * 128 + seg * 8);
        }
    };
    load_b(0, 0);
    cp_commit();

    for (int p = tid; p < 900; p += 256) tbl[p] = rpb[p];
    if (tid < 64) joff[tid] = (-(tid >> 3) * 15 - (tid & 7)) * 4;
    if (tid < 128) {
        int wim = (blockIdx.x * 2 + (tid >> 6)) & 1023;
        int r = (wim >> 5) * 8 + ((tid & 63) >> 3);
        int c = (wim & 31) * 8 + (tid & 7);
        int rr = (r < 248) ? 0 : ((r < 252) ? 1 : 2);
        int rc = (c < 248) ? 0 : ((c < 252) ? 1 : 2);
        lab[tid] = rr * 3 + rc;
    }

    // ---- LN1: staging -> bf16 A-tile (swizzled). warp per token ----
    cp_wait<1>();       // staging complete (b0 still in flight)
    __syncthreads();
    {
        float4 gv = ((const float4*)g1)[lane];
        float4 bv = ((const float4*)b1ln)[lane];
        #pragma unroll
        for (int it = 0; it < 16; it++) {
            int lt = it * 8 + wid;
            float4 v = *(const float4*)(sm + FQ_QOFF + lt * 512 + lane * 16);
            float s  = v.x + v.y + v.z + v.w;
            float sq = v.x*v.x + v.y*v.y + v.z*v.z + v.w*v.w;
            #pragma unroll
            for (int o = 16; o; o >>= 1) {
                s  += __shfl_xor_sync(0xffffffffu, s,  o);
                sq += __shfl_xor_sync(0xffffffffu, sq, o);
            }
            float mean = s * (1.0f / CCH);
            float var  = sq * (1.0f / CCH) - mean * mean;
            float rstd = rsqrtf(var + EPSV);
            float rx = (v.x - mean) * rstd * gv.x + bv.x;
            float ry = (v.y - mean) * rstd * gv.y + bv.y;
            float rz = (v.z - mean) * rstd * gv.z + bv.z;
            float rw = (v.w - mean) * rstd * gv.w + bv.w;
            uint2 pk;
            pk.x = pack_bf16(rx, ry);
            pk.y = pack_bf16(rz, rw);
            int seg = lane >> 1;
            *(uint2*)(sm + FQ_AOFF + lt * 256 + ((seg ^ (lt & 7)) << 4) + (lane & 1) * 8) = pk;
        }
    }

    const int lrow = lane & 15;
    const int lseg = lane >> 4;
    const int l4 = lane >> 2, lm = lane & 3;

    float d[2][8][4];
    #pragma unroll
    for (int mi = 0; mi < 2; mi++)
        #pragma unroll
        for (int ni = 0; ni < 8; ni++)
            #pragma unroll
            for (int r = 0; r < 4; r++) d[mi][ni][r] = 0.0f;

    for (int t = 0; t < 12; t++) {
        int buf = t & 1;
        if (t < 11) { load_b(t + 1, buf ^ 1); cp_commit(); cp_wait<1>(); }
        else cp_wait<0>();
        __syncthreads();
        uint32_t bbase = s_b + buf * 8192;
        #pragma unroll
        for (int ks = 0; ks < 2; ks++) {
            uint32_t a[2][4];
            #pragma unroll
            for (int mi = 0; mi < 2; mi++) {
                int row = wm * 32 + mi * 16 + lrow;
                int seg = (t & 3) * 4 + ks * 2 + lseg;
                ldm_x4(a[mi], s_a + row * 256 + ((seg ^ (row & 7)) << 4));
            }
            uint32_t b[4][4];
            #pragma unroll
            for (int bp = 0; bp < 4; bp++) {
                int row = ks * 16 + lrow;
                int seg = wn * 8 + bp * 2 + lseg;
                ldm_x4_t(b[bp], bbase + row * 256 + ((seg ^ (row & 7)) << 4));
            }
            #pragma unroll
            for (int mi = 0; mi < 2; mi++)
                #pragma unroll
                for (int ni = 0; ni < 8; ni++)
                    mma16816(d[mi][ni], a[mi], b[ni >> 1][(ni & 1) * 2], b[ni >> 1][(ni & 1) * 2 + 1]);
        }
        __syncthreads();
        if ((t & 3) == 3) {
            int bn = t >> 2;
            char* region = sm + FQ_QOFF + bn * 32768;
            #pragma unroll
            for (int mi = 0; mi < 2; mi++) {
                #pragma unroll
                for (int half = 0; half < 2; half++) {
                    int row = wm * 32 + mi * 16 + half * 8 + l4;
                    #pragma unroll
                    for (int ni = 0; ni < 8; ni++) {
                        int col = wn * 64 + ni * 8 + lm * 2;
                        float2 bsv = *(const float2*)(qkvb + bn * 128 + col);
                        float v0 = d[mi][ni][half * 2 + 0] + bsv.x;
                        float v1 = d[mi][ni][half * 2 + 1] + bsv.y;
                        *(uint32_t*)(region + row * 256 + (((col >> 3) ^ (row & 7)) << 4) + (col & 7) * 2)
                            = pack_bf16(v0, v1);
                        d[mi][ni][half * 2 + 0] = 0.0f;
                        d[mi][ni][half * 2 + 1] = 0.0f;
                    }
                }
            }
        }
    }
    __syncthreads();

    const uint32_t s_q = s_base + FQ_QOFF;
    const uint32_t s_k = s_base + FQ_KOFF;
    const uint32_t s_v = s_base + FQ_VOFF;
    const int h = wid >> 1, hhalf = wid & 1;
    const int mbase = hhalf * 32;
    const float scale = 0.17677669529663687f;

    for (int w = 0; w < 2; w++) {
        int wbase = w * 64;
        int wim = (blockIdx.x * 2 + w) & 1023;
        bool masked = ((wim >> 5) == 31) || ((wim & 31) == 31);

        float S[2][8][4];
        #pragma unroll
        for (int mi = 0; mi < 2; mi++)
            #pragma unroll
            for (int ni = 0; ni < 8; ni++)
                #pragma unroll
                for (int r = 0; r < 4; r++) S[mi][ni][r] = 0.0f;

        #pragma unroll
        for (int ks = 0; ks < 2; ks++) {
            uint32_t a[2][4], b[4][4];
            #pragma unroll
            for (int mi = 0; mi < 2; mi++) {
                int row = wbase + mbase + mi * 16 + lrow;
                int seg = h * 4 + ks * 2 + lseg;
                ldm_x4(a[mi], s_q + row * 256 + ((seg ^ (row & 7)) << 4));
            }
            #pragma unroll
            for (int nt = 0; nt < 4; nt++) {
                int row = wbase + nt * 16 + lrow;
                int seg = h * 4 + ks * 2 + lseg;
                ldm_x4(b[nt], s_k + row * 256 + ((seg ^ (row & 7)) << 4));
            }
            #pragma unroll
            for (int mi = 0; mi < 2; mi++)
                #pragma unroll
                for (int ni = 0; ni < 8; ni++)
                    mma16816(S[mi][ni], a[mi], b[ni >> 1][ni & 1], b[ni >> 1][(ni & 1) + 2]);
        }

        float sum[2][2];
        #pragma unroll
        for (int mi = 0; mi < 2; mi++) {
            #pragma unroll
            for (int rr = 0; rr < 2; rr++) {
                int i = mbase + mi * 16 + rr * 8 + l4;
                int rowbase = (((i >> 3) + 7) * 15 + ((i & 7) + 7)) * 4 + h;
                int li = lab[wbase + i];
                float m = -1e30f;
                #pragma unroll
                for (int ni = 0; ni < 8; ni++) {
                    int j0 = ni * 8 + lm * 2;
                    int idx0 = rowbase + joff[j0];
                    float v0 = S[mi][ni][rr * 2 + 0] * scale + tbl[idx0];
                    float v1 = S[mi][ni][rr * 2 + 1] * scale + tbl[idx0 - 4];
                    if (masked) {
                        if (lab[wbase + j0] != li)     v0 -= 100.0f;
                        if (lab[wbase + j0 + 1] != li) v1 -= 100.0f;
                    }
                    S[mi][ni][rr * 2 + 0] = v0;
                    S[mi][ni][rr * 2 + 1] = v1;
                    m = fmaxf(m, fmaxf(v0, v1));
                }
                m = fmaxf(m, __shfl_xor_sync(0xffffffffu, m, 1));
                m = fmaxf(m, __shfl_xor_sync(0xffffffffu, m, 2));
                float sm_ = 0.0f;
                #pragma unroll
                for (int ni = 0; ni < 8; ni++) {
                    #pragma unroll
                    for (int e = 0; e < 2; e++) {
                        float ev = __expf(S[mi][ni][rr * 2 + e] - m);
                        S[mi][ni][rr * 2 + e] = ev;
                        sm_ += ev;
                    }
                }
                sm_ += __shfl_xor_sync(0xffffffffu, sm_, 1);
                sm_ += __shfl_xor_sync(0xffffffffu, sm_, 2);
                sum[mi][rr] = sm_;
            }
        }

        uint32_t P[2][8][2];
        #pragma unroll
        for (int mi = 0; mi < 2; mi++)
            #pragma unroll
            for (int ni = 0; ni < 8; ni++) {
                P[mi][ni][0] = pack_bf16(S[mi][ni][0], S[mi][ni][1]);
                P[mi][ni][1] = pack_bf16(S[mi][ni][2], S[mi][ni][3]);
            }

        float o[2][4][4];
        #pragma unroll
        for (int mi = 0; mi < 2; mi++)
            #pragma unroll
            for (int nd = 0; nd < 4; nd++)
                #pragma unroll
                for (int r = 0; r < 4; r++) o[mi][nd][r] = 0.0f;

        #pragma unroll
        for (int kn = 0; kn < 4; kn++) {
            uint32_t vb[2][4];
            #pragma unroll
            for (int vp = 0; vp < 2; vp++) {
                int row = wbase + kn * 16 + lrow;
                int seg = h * 4 + vp * 2 + lseg;
                ldm_x4_t(vb[vp], s_v + row * 256 + ((seg ^ (row & 7)) << 4));
            }
            #pragma unroll
            for (int mi = 0; mi < 2; mi++) {
                uint32_t a[4] = { P[mi][2 * kn][0], P[mi][2 * kn][1],
                                  P[mi][2 * kn + 1][0], P[mi][2 * kn + 1][1] };
                #pragma unroll
                for (int nd = 0; nd < 4; nd++)
                    mma16816(o[mi][nd], a, vb[nd >> 1][(nd & 1) * 2], vb[nd >> 1][(nd & 1) * 2 + 1]);
            }
        }

        #pragma unroll
        for (int mi = 0; mi < 2; mi++) {
            #pragma unroll
            for (int rr = 0; rr < 2; rr++) {
                float inv = 1.0f / sum[mi][rr];
                size_t row = (size_t)(bm + wbase + mbase + mi * 16 + rr * 8 + l4);
                #pragma unroll
                for (int nd = 0; nd < 4; nd++) {
                    int col = h * 32 + nd * 8 + lm * 2;
                    *(uint32_t*)(out + row * 128 + col) =
                        pack_bf16(o[mi][nd][rr * 2] * inv, o[mi][nd][rr * 2 + 1] * inv);
                }
            }
        }
    }
}

// ---------------- proj GEMM (2 CTAs/SM) + residual + LN2 fusion ----------------
__global__ __launch_bounds__(256, 2) void proj_gemm(
    const __nv_bfloat16* __restrict__ A, const __nv_bfloat16* __restrict__ Bw,
    const float* __restrict__ bias, const float* __restrict__ extra, float* __restrict__ Cout,
    const float* __restrict__ g2, const float* __restrict__ b2, __nv_bfloat16* __restrict__ h2out)
{
    const int N = 128, K = 128;
    __shared__ __align__(128) __nv_bfloat16 As[2][128 * 32];
    __shared__ __align__(128) __nv_bfloat16 Bs[2][32 * 128];
    __shared__ float2 lnstat[128][2];

    const int tid  = threadIdx.x;
    const int lane = tid & 31;
    const int wid  = tid >> 5;
    const int wm   = wid & 3;
    const int wn   = wid >> 2;
    const int bm   = blockIdx.x * 128;

    const uint32_t s_a0 = smem_u32(As[0]);
    const uint32_t s_b0 = smem_u32(Bs[0]);

    auto load_chunk = [&](int c, int buf) {
        uint32_t abase = s_a0 + buf * 8192;
        #pragma unroll
        for (int r = 0; r < 2; r++) {
            int s = tid + r * 256;
            int row = s >> 2, seg = s & 3;
            cp_async16(abase + row * 64 + ((seg ^ ((row >> 1) & 3)) << 4),
                       A + (size_t)(bm + row) * K + c * 32 + seg * 8);
        }
        uint32_t bbase = s_b0 + buf * 8192;
        #pragma unroll
        for (int r = 0; r < 2; r++) {
            int s = tid + r * 256;
            int row = s >> 4, seg = s & 15;
            cp_async16(bbase + row * 256 + ((seg ^ (row & 7)) << 4),
                       Bw + (size_t)(c * 32 + row) * N + seg * 8);
        }
    };

    float d[2][8][4];
    #pragma unroll
    for (int mi = 0; mi < 2; mi++)
        #pragma unroll
        for (int ni = 0; ni < 8; ni++)
            #pragma unroll
            for (int r = 0; r < 4; r++) d[mi][ni][r] = 0.0f;

    load_chunk(0, 0);
    cp_commit();

    const int lrow = lane & 15;
    const int lseg = lane >> 4;

    for (int c = 0; c < 4; c++) {
        int buf = c & 1;
        if (c + 1 < 4) { load_chunk(c + 1, buf ^ 1); cp_commit(); cp_wait<1>(); }
        else cp_wait<0>();
        __syncthreads();
        uint32_t abase = s_a0 + buf * 8192;
        uint32_t bbase = s_b0 + buf * 8192;
        #pragma unroll
        for (int ks = 0; ks < 2; ks++) {
            uint32_t a[2][4];
            #pragma unroll
            for (int mi = 0; mi < 2; mi++) {
                int row = wm * 32 + mi * 16 + lrow;
                int seg = ks * 2 + lseg;
                ldm_x4(a[mi], abase + row * 64 + ((seg ^ ((row >> 1) & 3)) << 4));
            }
            uint32_t b[4][4];
            #pragma unroll
            for (int bp = 0; bp < 4; bp++) {
                int row = ks * 16 + lrow;
                int seg = wn * 8 + bp * 2 + lseg;
                ldm_x4_t(b[bp], bbase + row * 256 + ((seg ^ (row & 7)) << 4));
            }
            #pragma unroll
            for (int mi = 0; mi < 2; mi++)
                #pragma unroll
                for (int ni = 0; ni < 8; ni++)
                    mma16816(d[mi][ni], a[mi], b[ni >> 1][(ni & 1) * 2], b[ni >> 1][(ni & 1) * 2 + 1]);
        }
        __syncthreads();
    }

    const int l4 = lane >> 2, lm = lane & 3;
    float2 bs[8];
    #pragma unroll
    for (int ni = 0; ni < 8; ni++)
        bs[ni] = *(const float2*)(bias + wn * 64 + ni * 8 + lm * 2);

    size_t orows[2][2];
    #pragma unroll
    for (int mi = 0; mi < 2; mi++) {
        #pragma unroll
        for (int half = 0; half < 2; half++) {
            int row = bm + wm * 32 + mi * 16 + half * 8 + l4;
            size_t orow = calc_orow(row);
            orows[mi][half] = orow;
            float s = 0.0f, sq = 0.0f;
            #pragma unroll
            for (int ni = 0; ni < 8; ni++) {
                int col = wn * 64 + ni * 8 + lm * 2;
                float2 xr = *(const float2*)(extra + orow * 128 + col);
                float v0 = d[mi][ni][half * 2 + 0] + bs[ni].x + xr.x;
                float v1 = d[mi][ni][half * 2 + 1] + bs[ni].y + xr.y;
                d[mi][ni][half * 2 + 0] = v0;
                d[mi][ni][half * 2 + 1] = v1;
                s  += v0 + v1;
                sq += v0 * v0 + v1 * v1;
                float2 v; v.x = v0; v.y = v1;
                *(float2*)(Cout + orow * 128 + col) = v;
            }
            s  += __shfl_xor_sync(0xffffffffu, s,  1);
            sq += __shfl_xor_sync(0xffffffffu, sq, 1);
            s  += __shfl_xor_sync(0xffffffffu, s,  2);
            sq += __shfl_xor_sync(0xffffffffu, sq, 2);
            if (lm == 0) {
                float2 st; st.x = s; st.y = sq;
                lnstat[row - bm][wn] = st;
            }
        }
    }
    __syncthreads();
    float2 g2v[8], b2v[8];
    #pragma unroll
    for (int ni = 0; ni < 8; ni++) {
        g2v[ni] = *(const float2*)(g2 + wn * 64 + ni * 8 + lm * 2);
        b2v[ni] = *(const float2*)(b2 + wn * 64 + ni * 8 + lm * 2);
    }
    #pragma unroll
    for (int mi = 0; mi < 2; mi++) {
        #pragma unroll
        for (int half = 0; half < 2; half++) {
            int rl = wm * 32 + mi * 16 + half * 8 + l4;
            float2 sa = lnstat[rl][0], sb = lnstat[rl][1];
            float mean = (sa.x + sb.x) * (1.0f / CCH);
            float var  = (sa.y + sb.y) * (1.0f / CCH) - mean * mean;
            float rstd = rsqrtf(var + EPSV);
            size_t orow = orows[mi][half];
            #pragma unroll
            for (int ni = 0; ni < 8; ni++) {
                int col = wn * 64 + ni * 8 + lm * 2;
                float h0 = (d[mi][ni][half * 2 + 0] - mean) * rstd * g2v[ni].x + b2v[ni].x;
                float h1 = (d[mi][ni][half * 2 + 1] - mean) * rstd * g2v[ni].y + b2v[ni].y;
                *(uint32_t*)(h2out + orow * 128 + col) = pack_bf16(h0, h1);
            }
        }
    }
}

// ---------------- MLP GEMMs: BM=128 BN=128 BK=32, 2 CTAs/SM --------------------
template<int EPI, int K, int N>
__global__ __launch_bounds__(256, 2) void fc_gemm(
    const __nv_bfloat16* __restrict__ A, const __nv_bfloat16* __restrict__ Bw,
    const float* __restrict__ bias, const float* __restrict__ extra, void* __restrict__ Cout)
{
    __shared__ __align__(128) __nv_bfloat16 As[2][128 * 32];
    __shared__ __align__(128) __nv_bfloat16 Bs[2][32 * 128];

    const int tid  = threadIdx.x;
    const int lane = tid & 31;
    const int wid  = tid >> 5;
    const int wm   = wid & 3;
    const int wn   = wid >> 2;
    const int bm   = blockIdx.y * 128;
    const int bn   = blockIdx.x * 128;

    const uint32_t s_a0 = smem_u32(As[0]);
    const uint32_t s_b0 = smem_u32(Bs[0]);

    auto load_chunk = [&](int c, int buf) {
        uint32_t abase = s_a0 + buf * 8192;
        #pragma unroll
        for (int r = 0; r < 2; r++) {
            int s = tid + r * 256;
            int row = s >> 2, seg = s & 3;
            cp_async16(abase + row * 64 + ((seg ^ ((row >> 1) & 3)) << 4),
                       A + (size_t)(bm + row) * K + c * 32 + seg * 8);
        }
        uint32_t bbase = s_b0 + buf * 8192;
        #pragma unroll
        for (int r = 0; r < 2; r++) {
            int s = tid + r * 256;
            int row = s >> 4, seg = s & 15;
            cp_async16(bbase + row * 256 + ((seg ^ (row & 7)) << 4),
                       Bw + (size_t)(c * 32 + row) * N + bn + seg * 8);
        }
    };

    float d[2][8][4];
    #pragma unroll
    for (int mi = 0; mi < 2; mi++)
        #pragma unroll
        for (int ni = 0; ni < 8; ni++)
            #pragma unroll
            for (int r = 0; r < 4; r++) d[mi][ni][r] = 0.0f;

    load_chunk(0, 0);
    cp_commit();

    const int lrow = lane & 15;
    const int lseg = lane >> 4;
    const int NCH = K / 32;

    for (int c = 0; c < NCH; c++) {
        int buf = c & 1;
        if (c + 1 < NCH) { load_chunk(c + 1, buf ^ 1); cp_commit(); cp_wait<1>(); }
        else cp_wait<0>();
        __syncthreads();
        uint32_t abase = s_a0 + buf * 8192;
        uint32_t bbase = s_b0 + buf * 8192;
        #pragma unroll
        for (int ks = 0; ks < 2; ks++) {
            uint32_t a[2][4];
            #pragma unroll
            for (int mi = 0; mi < 2; mi++) {
                int row = wm * 32 + mi * 16 + lrow;
                int seg = ks * 2 + lseg;
                ldm_x4(a[mi], abase + row * 64 + ((seg ^ ((row >> 1) & 3)) << 4));
            }
            uint32_t b[4][4];
            #pragma unroll
            for (int bp = 0; bp < 4; bp++) {
                int row = ks * 16 + lrow;
                int seg = wn * 8 + bp * 2 + lseg;
                ldm_x4_t(b[bp], bbase + row * 256 + ((seg ^ (row & 7)) << 4));
            }
            #pragma unroll
            for (int mi = 0; mi < 2; mi++)
                #pragma unroll
                for (int ni = 0; ni < 8; ni++)
                    mma16816(d[mi][ni], a[mi], b[ni >> 1][(ni & 1) * 2], b[ni >> 1][(ni & 1) * 2 + 1]);
        }
        __syncthreads();
    }

    const int l4 = lane >> 2, lm = lane & 3;
    float2 bs[8];
    #pragma unroll
    for (int ni = 0; ni < 8; ni++)
        bs[ni] = *(const float2*)(bias + bn + wn * 64 + ni * 8 + lm * 2);

    #pragma unroll
    for (int mi = 0; mi < 2; mi++) {
        #pragma unroll
        for (int half = 0; half < 2; half++) {
            int row = bm + wm * 32 + mi * 16 + half * 8 + l4;
            if (EPI == 2) {
                __nv_bfloat16* C = (__nv_bfloat16*)Cout;
                #pragma unroll
                for (int ni = 0; ni < 8; ni++) {
                    int col = bn + wn * 64 + ni * 8 + lm * 2;
                    float v0 = gelu_fast(d[mi][ni][half * 2 + 0] + bs[ni].x);
                    float v1 = gelu_fast(d[mi][ni][half * 2 + 1] + bs[ni].y);
                    *(uint32_t*)(C + (size_t)row * N + col) = pack_bf16(v0, v1);
                }
            } else {
                float* C = (float*)Cout;
                #pragma unroll
                for (int ni = 0; ni < 8; ni++) {
                    int col = bn + wn * 64 + ni * 8 + lm * 2;
                    float2 res = *(const float2*)(extra + (size_t)row * 128 + col);
                    float2 v;
                    v.x = d[mi][ni][half * 2 + 0] + bs[ni].x + res.x;
                    v.y = d[mi][ni][half * 2 + 1] + bs[ni].y + res.y;
                    *(float2*)(C + (size_t)row * 128 + col) = v;
                }
            }
        }
    }
}

// ---------------- launch ----------------
extern "C" void kernel_launch(void* const* d_in, const int* in_sizes, int n_in,
                              void* d_out, int out_size) {
    const float* x      = (const float*)d_in[0];
    const float* gamma1 = (const float*)d_in[1];
    const float* beta1  = (const float*)d_in[2];
    const float* qkv_w  = (const float*)d_in[3];
    const float* qkv_b  = (const float*)d_in[4];
    const float* proj_w = (const float*)d_in[5];
    const float* proj_b = (const float*)d_in[6];
    const float* rpb    = (const float*)d_in[7];
    const float* gamma2 = (const float*)d_in[8];
    const float* beta2  = (const float*)d_in[9];
    const float* w1     = (const float*)d_in[10];
    const float* b1     = (const float*)d_in[11];
    const float* w2     = (const float*)d_in[12];
    const float* b2     = (const float*)d_in[13];
    float* out = (float*)d_out;

    __nv_bfloat16 *att, *h2, *m1, *wq, *wp, *w1b, *w2b;
    float *y1;
    cudaGetSymbolAddress((void**)&att, g_att);
    cudaGetSymbolAddress((void**)&y1,  g_y1);
    cudaGetSymbolAddress((void**)&h2,  g_h2);
    cudaGetSymbolAddress((void**)&m1,  g_m1);
    cudaGetSymbolAddress((void**)&wq,  g_wq);
    cudaGetSymbolAddress((void**)&wp,  g_wp);
    cudaGetSymbolAddress((void**)&w1b, g_w1b);
    cudaGetSymbolAddress((void**)&w2b, g_w2b);

    cudaFuncSetAttribute(fused_qkv_attn, cudaFuncAttributeMaxDynamicSharedMemorySize, FQ_SMEM);

    convw_kernel<<<49152 / 256, 256>>>(qkv_w, wq, proj_w, wp, w1, w1b, w2, w2b);

    // 1. fused LN1 + qkv GEMM + window attention
    fused_qkv_attn<<<TOK / 128, 256, FQ_SMEM>>>(x, gamma1, beta1, wq, qkv_b, rpb, att);
    // 2. proj GEMM + window reverse + residual -> y1 fp32, fused LN2 -> h2 bf16
    proj_gemm<<<TOK / 128, 256>>>(att, wp, proj_b, x, y1, gamma2, beta2, h2);
    // 3. fc1 + GELU -> m1 bf16   [T,128]@[128,512]
    fc_gemm<2, 128, 512><<<dim3(4, TOK / 128), 256>>>(h2, w1b, b1, nullptr, m1);
    // 4. fc2 + residual -> out   [T,512]@[512,128]
    fc_gemm<3, 512, 128><<<dim3(1, TOK / 128), 256>>>(m1, w2b, b2, y1, out);
}

// round 15
// speedup vs baseline: 1.0461x; 1.0461x over previous
#include <cuda_runtime.h>
#include <cuda_bf16.h>
#include <math.h>
#include <cstdint>

#define BATCH 4
#define HIMG 256
#define WIMG 256
#define CCH 128
#define TOK (BATCH*HIMG*WIMG)   // 262144
#define EPSV 1.001e-05f

// ---------------- scratch ----------------
__device__ __align__(16) __nv_bfloat16 g_att[ (size_t)TOK*CCH ];
__device__ __align__(16) float         g_y1 [ (size_t)TOK*CCH ];
__device__ __align__(16) __nv_bfloat16 g_h2 [ (size_t)TOK*CCH ];
__device__ __align__(16) __nv_bfloat16 g_m1 [ (size_t)TOK*4*CCH ];
__device__ __align__(16) __nv_bfloat16 g_wq [ 128*384 ];
__device__ __align__(16) __nv_bfloat16 g_wp [ 128*128 ];
__device__ __align__(16) __nv_bfloat16 g_w1b[ 128*512 ];
__device__ __align__(16) __nv_bfloat16 g_w2b[ 512*128 ];

// ---------------- helpers ----------------
__device__ __forceinline__ uint32_t smem_u32(const void* p) {
    uint32_t a;
    asm("{ .reg .u64 t; cvta.to.shared.u64 t, %1; cvt.u32.u64 %0, t; }" : "=r"(a) : "l"(p));
    return a;
}
__device__ __forceinline__ uint32_t pack_bf16(float lo, float hi) {
    uint32_t r;
    asm("cvt.rn.bf16x2.f32 %0, %1, %2;" : "=r"(r) : "f"(hi), "f"(lo));
    return r;
}
__device__ __forceinline__ void cp_async16(uint32_t dst, const void* src) {
    asm volatile("cp.async.cg.shared.global [%0], [%1], 16;" :: "r"(dst), "l"(src));
}
__device__ __forceinline__ void cp_commit() { asm volatile("cp.async.commit_group;"); }
template<int N>
__device__ __forceinline__ void cp_wait() { asm volatile("cp.async.wait_group %0;" :: "n"(N)); }

__device__ __forceinline__ void st_cs_u32(void* p, uint32_t v) {
    asm volatile("st.global.cs.u32 [%0], %1;" :: "l"(p), "r"(v));
}
__device__ __forceinline__ void st_cs_f2(void* p, float2 v) {
    asm volatile("st.global.cs.v2.f32 [%0], {%1,%2};" :: "l"(p), "f"(v.x), "f"(v.y));
}

__device__ __forceinline__ void ldm_x4(uint32_t* r, uint32_t a) {
    asm volatile("ldmatrix.sync.aligned.m8n8.x4.shared.b16 {%0,%1,%2,%3}, [%4];"
        : "=r"(r[0]), "=r"(r[1]), "=r"(r[2]), "=r"(r[3]) : "r"(a));
}
__device__ __forceinline__ void ldm_x4_t(uint32_t* r, uint32_t a) {
    asm volatile("ldmatrix.sync.aligned.m8n8.x4.trans.shared.b16 {%0,%1,%2,%3}, [%4];"
        : "=r"(r[0]), "=r"(r[1]), "=r"(r[2]), "=r"(r[3]) : "r"(a));
}
__device__ __forceinline__ void mma16816(float* d, const uint32_t* a, uint32_t b0, uint32_t b1) {
    asm volatile("mma.sync.aligned.m16n8k16.row.col.f32.bf16.bf16.f32 "
        "{%0,%1,%2,%3}, {%4,%5,%6,%7}, {%8,%9}, {%0,%1,%2,%3};"
        : "+f"(d[0]), "+f"(d[1]), "+f"(d[2]), "+f"(d[3])
        : "r"(a[0]), "r"(a[1]), "r"(a[2]), "r"(a[3]), "r"(b0), "r"(b1));
}
// fast GELU: tanh form with HW tanh.approx
__device__ __forceinline__ float gelu_fast(float x) {
    float t = 0.79788456080286536f * (x + 0.044715f * x * x * x);
    float th;
    asm("tanh.approx.f32 %0, %1;" : "=f"(th) : "f"(t));
    return 0.5f * x * (1.0f + th);
}
// window-layout row -> image row (window reverse + unshift)
__device__ __forceinline__ size_t calc_orow(int row) {
    int win = row >> 6, r6 = row & 63;
    int bi = win >> 10, wim = win & 1023;
    int wh = wim >> 5, wc = wim & 31;
    int ii = r6 >> 3, jj = r6 & 7;
    int oh = (wh * 8 + ii + 4) & 255;
    int ow = (wc * 8 + jj + 4) & 255;
    return ((size_t)(bi * 256 + oh) * 256 + ow);
}

// ---------------- fp32 -> bf16 weight convert ----------------------------------
__global__ void convw_kernel(const float* __restrict__ w0, __nv_bfloat16* __restrict__ t0,
                             const float* __restrict__ w1, __nv_bfloat16* __restrict__ t1,
                             const float* __restrict__ w2, __nv_bfloat16* __restrict__ t2,
                             const float* __restrict__ w3, __nv_bfloat16* __restrict__ t3) {
    int i = blockIdx.x * 256 + threadIdx.x;
    const float* w; __nv_bfloat16* t; int base;
    if (i < 12288)      { w = w0; t = t0; base = 0; }
    else if (i < 16384) { w = w1; t = t1; base = 12288; }
    else if (i < 32768) { w = w2; t = t2; base = 16384; }
    else                { w = w3; t = t3; base = 32768; }
    int j = i - base;
    float4 v = ((const float4*)w)[j];
    uint2 p;
    p.x = pack_bf16(v.x, v.y);
    p.y = pack_bf16(v.z, v.w);
    *(uint2*)(t + (size_t)j * 4) = p;
}

// ---------------- fused LN1 + qkv GEMM + window attention ----------------------
// B pipeline: 3 stages, single sync per chunk.
#define FQ_AOFF 0
#define FQ_BOFF 32768        // 3 x 8KB
#define FQ_QOFF 57344        // doubles as fp32 x-staging (64KB over q+k)
#define FQ_KOFF 90112
#define FQ_VOFF 122880
#define FQ_TOFF 155648
#define FQ_LOFF 159248
#define FQ_JOFF 159760
#define FQ_SMEM 160016

__global__ __launch_bounds__(256) void fused_qkv_attn(
    const float* __restrict__ x, const float* __restrict__ g1, const float* __restrict__ b1ln,
    const __nv_bfloat16* __restrict__ wq,
    const float* __restrict__ qkvb, const float* __restrict__ rpb,
    __nv_bfloat16* __restrict__ out)
{
    extern __shared__ char sm[];
    float* tbl  = (float*)(sm + FQ_TOFF);
    int*   lab  = (int*)(sm + FQ_LOFF);
    int*   joff = (int*)(sm + FQ_JOFF);

    const int tid  = threadIdx.x;
    const int lane = tid & 31;
    const int wid  = tid >> 5;
    const int wm   = wid & 3;
    const int wn   = wid >> 2;
    const int bm   = blockIdx.x * 128;

    const uint32_t s_base = smem_u32(sm);
    const uint32_t s_a = s_base + FQ_AOFF;
    const uint32_t s_b = s_base + FQ_BOFF;
    const uint32_t s_x = s_base + FQ_QOFF;   // fp32 staging, consumed before q is written

    // stage x rows (gathered via window reverse): 128 tokens x 512B  [group 0]
    #pragma unroll
    for (int u = 0; u < 16; u++) {
        int s = u * 256 + tid;          // 0..4095
        int lt = s >> 5, seg = s & 31;
        size_t orow = calc_orow(bm + lt);
        cp_async16(s_x + lt * 512 + seg * 16, x + orow * 128 + seg * 4);
    }
    cp_commit();

    auto load_b = [&](int t, int buf) {
        uint32_t bbase = s_b + buf * 8192;
        #pragma unroll
        for (int r2 = 0; r2 < 2; r2++) {
            int s = tid + r2 * 256;
            int row = s >> 4, seg = s & 15;
            cp_async16(bbase + row * 256 + ((seg ^ (row & 7)) << 4),
                       wq + (size_t)((t & 3) * 32 + row) * 384 + (t >> 2) * 128 + seg * 8);
        }
    };
    load_b(0, 0); cp_commit();   // group 1
    load_b(1, 1); cp_commit();   // group 2

    for (int p = tid; p < 900; p += 256) tbl[p] = rpb[p];
    if (tid < 64) joff[tid] = (-(tid >> 3) * 15 - (tid & 7)) * 4;
    if (tid < 128) {
        int wim = (blockIdx.x * 2 + (tid >> 6)) & 1023;
        int r = (wim >> 5) * 8 + ((tid & 63) >> 3);
        int c = (wim & 31) * 8 + (tid & 7);
        int rr = (r < 248) ? 0 : ((r < 252) ? 1 : 2);
        int rc = (c < 248) ? 0 : ((c < 252) ? 1 : 2);
        lab[tid] = rr * 3 + rc;
    }

    // ---- LN1: staging -> bf16 A-tile (swizzled). warp per token ----
    cp_wait<2>();       // staging (group 0) complete; b0/b1 may be in flight
    __syncthreads();
    {
        float4 gv = ((const float4*)g1)[lane];
        float4 bv = ((const float4*)b1ln)[lane];
        #pragma unroll
        for (int it = 0; it < 16; it++) {
            int lt = it * 8 + wid;
            float4 v = *(const float4*)(sm + FQ_QOFF + lt * 512 + lane * 16);
            float s  = v.x + v.y + v.z + v.w;
            float sq = v.x*v.x + v.y*v.y + v.z*v.z + v.w*v.w;
            #pragma unroll
            for (int o = 16; o; o >>= 1) {
                s  += __shfl_xor_sync(0xffffffffu, s,  o);
                sq += __shfl_xor_sync(0xffffffffu, sq, o);
            }
            float mean = s * (1.0f / CCH);
            float var  = sq * (1.0f / CCH) - mean * mean;
            float rstd = rsqrtf(var + EPSV);
            float rx = (v.x - mean) * rstd * gv.x + bv.x;
            float ry = (v.y - mean) * rstd * gv.y + bv.y;
            float rz = (v.z - mean) * rstd * gv.z + bv.z;
            float rw = (v.w - mean) * rstd * gv.w + bv.w;
            uint2 pk;
            pk.x = pack_bf16(rx, ry);
            pk.y = pack_bf16(rz, rw);
            int seg = lane >> 1;
            *(uint2*)(sm + FQ_AOFF + lt * 256 + ((seg ^ (lt & 7)) << 4) + (lane & 1) * 8) = pk;
        }
    }

    const int lrow = lane & 15;
    const int lseg = lane >> 4;
    const int l4 = lane >> 2, lm = lane & 3;

    float d[2][8][4];
    #pragma unroll
    for (int mi = 0; mi < 2; mi++)
        #pragma unroll
        for (int ni = 0; ni < 8; ni++)
            #pragma unroll
            for (int r = 0; r < 4; r++) d[mi][ni][r] = 0.0f;

    // ---- qkv GEMM: 12 chunks, 3-stage pipeline, 1 sync per chunk ----
    for (int t = 0; t < 12; t++) {
        if (t == 11) cp_wait<0>(); else cp_wait<1>();
        __syncthreads();    // chunk t visible; buffer (t+2)%3 free (read at t-1)
        if (t + 2 < 12) { load_b(t + 2, (t + 2) % 3); cp_commit(); }
        uint32_t bbase = s_b + (t % 3) * 8192;
        #pragma unroll
        for (int ks = 0; ks < 2; ks++) {
            uint32_t a[2][4];
            #pragma unroll
            for (int mi = 0; mi < 2; mi++) {
                int row = wm * 32 + mi * 16 + lrow;
                int seg = (t & 3) * 4 + ks * 2 + lseg;
                ldm_x4(a[mi], s_a + row * 256 + ((seg ^ (row & 7)) << 4));
            }
            uint32_t b[4][4];
            #pragma unroll
            for (int bp = 0; bp < 4; bp++) {
                int row = ks * 16 + lrow;
                int seg = wn * 8 + bp * 2 + lseg;
                ldm_x4_t(b[bp], bbase + row * 256 + ((seg ^ (row & 7)) << 4));
            }
            #pragma unroll
            for (int mi = 0; mi < 2; mi++)
                #pragma unroll
                for (int ni = 0; ni < 8; ni++)
                    mma16816(d[mi][ni], a[mi], b[ni >> 1][(ni & 1) * 2], b[ni >> 1][(ni & 1) * 2 + 1]);
        }
        if ((t & 3) == 3) {
            // qkv store: each warp writes only its own output rows -> no sync needed
            int bn = t >> 2;
            char* region = sm + FQ_QOFF + bn * 32768;
            #pragma unroll
            for (int mi = 0; mi < 2; mi++) {
                #pragma unroll
                for (int half = 0; half < 2; half++) {
                    int row = wm * 32 + mi * 16 + half * 8 + l4;
                    #pragma unroll
                    for (int ni = 0; ni < 8; ni++) {
                        int col = wn * 64 + ni * 8 + lm * 2;
                        float2 bsv = *(const float2*)(qkvb + bn * 128 + col);
                        float v0 = d[mi][ni][half * 2 + 0] + bsv.x;
                        float v1 = d[mi][ni][half * 2 + 1] + bsv.y;
                        *(uint32_t*)(region + row * 256 + (((col >> 3) ^ (row & 7)) << 4) + (col & 7) * 2)
                            = pack_bf16(v0, v1);
                        d[mi][ni][half * 2 + 0] = 0.0f;
                        d[mi][ni][half * 2 + 1] = 0.0f;
                    }
                }
            }
        }
    }
    __syncthreads();

    const uint32_t s_q = s_base + FQ_QOFF;
    const uint32_t s_k = s_base + FQ_KOFF;
    const uint32_t s_v = s_base + FQ_VOFF;
    const int h = wid >> 1, hhalf = wid & 1;
    const int mbase = hhalf * 32;
    const float scale = 0.17677669529663687f;

    for (int w = 0; w < 2; w++) {
        int wbase = w * 64;
        int wim = (blockIdx.x * 2 + w) & 1023;
        bool masked = ((wim >> 5) == 31) || ((wim & 31) == 31);

        float S[2][8][4];
        #pragma unroll
        for (int mi = 0; mi < 2; mi++)
            #pragma unroll
            for (int ni = 0; ni < 8; ni++)
                #pragma unroll
                for (int r = 0; r < 4; r++) S[mi][ni][r] = 0.0f;

        #pragma unroll
        for (int ks = 0; ks < 2; ks++) {
            uint32_t a[2][4], b[4][4];
            #pragma unroll
            for (int mi = 0; mi < 2; mi++) {
                int row = wbase + mbase + mi * 16 + lrow;
                int seg = h * 4 + ks * 2 + lseg;
                ldm_x4(a[mi], s_q + row * 256 + ((seg ^ (row & 7)) << 4));
            }
            #pragma unroll
            for (int nt = 0; nt < 4; nt++) {
                int row = wbase + nt * 16 + lrow;
                int seg = h * 4 + ks * 2 + lseg;
                ldm_x4(b[nt], s_k + row * 256 + ((seg ^ (row & 7)) << 4));
            }
            #pragma unroll
            for (int mi = 0; mi < 2; mi++)
                #pragma unroll
                for (int ni = 0; ni < 8; ni++)
                    mma16816(S[mi][ni], a[mi], b[ni >> 1][ni & 1], b[ni >> 1][(ni & 1) + 2]);
        }

        float sum[2][2];
        #pragma unroll
        for (int mi = 0; mi < 2; mi++) {
            #pragma unroll
            for (int rr = 0; rr < 2; rr++) {
                int i = mbase + mi * 16 + rr * 8 + l4;
                int rowbase = (((i >> 3) + 7) * 15 + ((i & 7) + 7)) * 4 + h;
                int li = lab[wbase + i];
                float m = -1e30f;
                #pragma unroll
                for (int ni = 0; ni < 8; ni++) {
                    int j0 = ni * 8 + lm * 2;
                    int idx0 = rowbase + joff[j0];
                    float v0 = S[mi][ni][rr * 2 + 0] * scale + tbl[idx0];
                    float v1 = S[mi][ni][rr * 2 + 1] * scale + tbl[idx0 - 4];
                    if (masked) {
                        if (lab[wbase + j0] != li)     v0 -= 100.0f;
                        if (lab[wbase + j0 + 1] != li) v1 -= 100.0f;
                    }
                    S[mi][ni][rr * 2 + 0] = v0;
                    S[mi][ni][rr * 2 + 1] = v1;
                    m = fmaxf(m, fmaxf(v0, v1));
                }
                m = fmaxf(m, __shfl_xor_sync(0xffffffffu, m, 1));
                m = fmaxf(m, __shfl_xor_sync(0xffffffffu, m, 2));
                float sm_ = 0.0f;
                #pragma unroll
                for (int ni = 0; ni < 8; ni++) {
                    #pragma unroll
                    for (int e = 0; e < 2; e++) {
                        float ev = __expf(S[mi][ni][rr * 2 + e] - m);
                        S[mi][ni][rr * 2 + e] = ev;
                        sm_ += ev;
                    }
                }
                sm_ += __shfl_xor_sync(0xffffffffu, sm_, 1);
                sm_ += __shfl_xor_sync(0xffffffffu, sm_, 2);
                sum[mi][rr] = sm_;
            }
        }

        uint32_t P[2][8][2];
        #pragma unroll
        for (int mi = 0; mi < 2; mi++)
            #pragma unroll
            for (int ni = 0; ni < 8; ni++) {
                P[mi][ni][0] = pack_bf16(S[mi][ni][0], S[mi][ni][1]);
                P[mi][ni][1] = pack_bf16(S[mi][ni][2], S[mi][ni][3]);
            }

        float o[2][4][4];
        #pragma unroll
        for (int mi = 0; mi < 2; mi++)
            #pragma unroll
            for (int nd = 0; nd < 4; nd++)
                #pragma unroll
                for (int r = 0; r < 4; r++) o[mi][nd][r] = 0.0f;

        #pragma unroll
        for (int kn = 0; kn < 4; kn++) {
            uint32_t vb[2][4];
            #pragma unroll
            for (int vp = 0; vp < 2; vp++) {
                int row = wbase + kn * 16 + lrow;
                int seg = h * 4 + vp * 2 + lseg;
                ldm_x4_t(vb[vp], s_v + row * 256 + ((seg ^ (row & 7)) << 4));
            }
            #pragma unroll
            for (int mi = 0; mi < 2; mi++) {
                uint32_t a[4] = { P[mi][2 * kn][0], P[mi][2 * kn][1],
                                  P[mi][2 * kn + 1][0], P[mi][2 * kn + 1][1] };
                #pragma unroll
                for (int nd = 0; nd < 4; nd++)
                    mma16816(o[mi][nd], a, vb[nd >> 1][(nd & 1) * 2], vb[nd >> 1][(nd & 1) * 2 + 1]);
            }
        }

        #pragma unroll
        for (int mi = 0; mi < 2; mi++) {
            #pragma unroll
            for (int rr = 0; rr < 2; rr++) {
                float inv = 1.0f / sum[mi][rr];
                size_t row = (size_t)(bm + wbase + mbase + mi * 16 + rr * 8 + l4);
                #pragma unroll
                for (int nd = 0; nd < 4; nd++) {
                    int col = h * 32 + nd * 8 + lm * 2;
                    *(uint32_t*)(out + row * 128 + col) =
                        pack_bf16(o[mi][nd][rr * 2] * inv, o[mi][nd][rr * 2 + 1] * inv);
                }
            }
        }
    }
}

// ---------------- proj GEMM (2 CTAs/SM) + residual + LN2 fusion ----------------
__global__ __launch_bounds__(256, 2) void proj_gemm(
    const __nv_bfloat16* __restrict__ A, const __nv_bfloat16* __restrict__ Bw,
    const float* __restrict__ bias, const float* __restrict__ extra, float* __restrict__ Cout,
    const float* __restrict__ g2, const float* __restrict__ b2, __nv_bfloat16* __restrict__ h2out)
{
    const int N = 128, K = 128;
    __shared__ __align__(128) __nv_bfloat16 As[2][128 * 32];
    __shared__ __align__(128) __nv_bfloat16 Bs[2][32 * 128];
    __shared__ float2 lnstat[128][2];

    const int tid  = threadIdx.x;
    const int lane = tid & 31;
    const int wid  = tid >> 5;
    const int wm   = wid & 3;
    const int wn   = wid >> 2;
    const int bm   = blockIdx.x * 128;

    const uint32_t s_a0 = smem_u32(As[0]);
    const uint32_t s_b0 = smem_u32(Bs[0]);

    auto load_chunk = [&](int c, int buf) {
        uint32_t abase = s_a0 + buf * 8192;
        #pragma unroll
        for (int r = 0; r < 2; r++) {
            int s = tid + r * 256;
            int row = s >> 2, seg = s & 3;
            cp_async16(abase + row * 64 + ((seg ^ ((row >> 1) & 3)) << 4),
                       A + (size_t)(bm + row) * K + c * 32 + seg * 8);
        }
        uint32_t bbase = s_b0 + buf * 8192;
        #pragma unroll
        for (int r = 0; r < 2; r++) {
            int s = tid + r * 256;
            int row = s >> 4, seg = s & 15;
            cp_async16(bbase + row * 256 + ((seg ^ (row & 7)) << 4),
                       Bw + (size_t)(c * 32 + row) * N + seg * 8);
        }
    };

    float d[2][8][4];
    #pragma unroll
    for (int mi = 0; mi < 2; mi++)
        #pragma unroll
        for (int ni = 0; ni < 8; ni++)
            #pragma unroll
            for (int r = 0; r < 4; r++) d[mi][ni][r] = 0.0f;

    load_chunk(0, 0);
    cp_commit();

    const int lrow = lane & 15;
    const int lseg = lane >> 4;

    for (int c = 0; c < 4; c++) {
        int buf = c & 1;
        if (c + 1 < 4) { load_chunk(c + 1, buf ^ 1); cp_commit(); cp_wait<1>(); }
        else cp_wait<0>();
        __syncthreads();
        uint32_t abase = s_a0 + buf * 8192;
        uint32_t bbase = s_b0 + buf * 8192;
        #pragma unroll
        for (int ks = 0; ks < 2; ks++) {
            uint32_t a[2][4];
            #pragma unroll
            for (int mi = 0; mi < 2; mi++) {
                int row = wm * 32 + mi * 16 + lrow;
                int seg = ks * 2 + lseg;
                ldm_x4(a[mi], abase + row * 64 + ((seg ^ ((row >> 1) & 3)) << 4));
            }
            uint32_t b[4][4];
            #pragma unroll
            for (int bp = 0; bp < 4; bp++) {
                int row = ks * 16 + lrow;
                int seg = wn * 8 + bp * 2 + lseg;
                ldm_x4_t(b[bp], bbase + row * 256 + ((seg ^ (row & 7)) << 4));
            }
            #pragma unroll
            for (int mi = 0; mi < 2; mi++)
                #pragma unroll
                for (int ni = 0; ni < 8; ni++)
                    mma16816(d[mi][ni], a[mi], b[ni >> 1][(ni & 1) * 2], b[ni >> 1][(ni & 1) * 2 + 1]);
        }
        __syncthreads();
    }

    const int l4 = lane >> 2, lm = lane & 3;
    float2 bs[8];
    #pragma unroll
    for (int ni = 0; ni < 8; ni++)
        bs[ni] = *(const float2*)(bias + wn * 64 + ni * 8 + lm * 2);

    size_t orows[2][2];
    #pragma unroll
    for (int mi = 0; mi < 2; mi++) {
        #pragma unroll
        for (int half = 0; half < 2; half++) {
            int row = bm + wm * 32 + mi * 16 + half * 8 + l4;
            size_t orow = calc_orow(row);
            orows[mi][half] = orow;
            float s = 0.0f, sq = 0.0f;
            #pragma unroll
            for (int ni = 0; ni < 8; ni++) {
                int col = wn * 64 + ni * 8 + lm * 2;
                float2 xr = *(const float2*)(extra + orow * 128 + col);
                float v0 = d[mi][ni][half * 2 + 0] + bs[ni].x + xr.x;
                float v1 = d[mi][ni][half * 2 + 1] + bs[ni].y + xr.y;
                d[mi][ni][half * 2 + 0] = v0;
                d[mi][ni][half * 2 + 1] = v1;
                s  += v0 + v1;
                sq += v0 * v0 + v1 * v1;
                float2 v; v.x = v0; v.y = v1;
                *(float2*)(Cout + orow * 128 + col) = v;
            }
            s  += __shfl_xor_sync(0xffffffffu, s,  1);
            sq += __shfl_xor_sync(0xffffffffu, sq, 1);
            s  += __shfl_xor_sync(0xffffffffu, s,  2);
            sq += __shfl_xor_sync(0xffffffffu, sq, 2);
            if (lm == 0) {
                float2 st; st.x = s; st.y = sq;
                lnstat[row - bm][wn] = st;
            }
        }
    }
    __syncthreads();
    float2 g2v[8], b2v[8];
    #pragma unroll
    for (int ni = 0; ni < 8; ni++) {
        g2v[ni] = *(const float2*)(g2 + wn * 64 + ni * 8 + lm * 2);
        b2v[ni] = *(const float2*)(b2 + wn * 64 + ni * 8 + lm * 2);
    }
    #pragma unroll
    for (int mi = 0; mi < 2; mi++) {
        #pragma unroll
        for (int half = 0; half < 2; half++) {
            int rl = wm * 32 + mi * 16 + half * 8 + l4;
            float2 sa = lnstat[rl][0], sb = lnstat[rl][1];
            float mean = (sa.x + sb.x) * (1.0f / CCH);
            float var  = (sa.y + sb.y) * (1.0f / CCH) - mean * mean;
            float rstd = rsqrtf(var + EPSV);
            size_t orow = orows[mi][half];
            #pragma unroll
            for (int ni = 0; ni < 8; ni++) {
                int col = wn * 64 + ni * 8 + lm * 2;
                float h0 = (d[mi][ni][half * 2 + 0] - mean) * rstd * g2v[ni].x + b2v[ni].x;
                float h1 = (d[mi][ni][half * 2 + 1] - mean) * rstd * g2v[ni].y + b2v[ni].y;
                *(uint32_t*)(h2out + orow * 128 + col) = pack_bf16(h0, h1);
            }
        }
    }
}

// ---------------- MLP GEMMs: 3-stage pipeline, 1 sync/chunk, 2 CTAs/SM ---------
template<int EPI, int K, int N>
__global__ __launch_bounds__(256, 2) void fc_gemm(
    const __nv_bfloat16* __restrict__ A, const __nv_bfloat16* __restrict__ Bw,
    const float* __restrict__ bias, const float* __restrict__ extra, void* __restrict__ Cout)
{
    __shared__ __align__(128) __nv_bfloat16 As[3][128 * 32];
    __shared__ __align__(128) __nv_bfloat16 Bs[3][32 * 128];

    const int tid  = threadIdx.x;
    const int lane = tid & 31;
    const int wid  = tid >> 5;
    const int wm   = wid & 3;
    const int wn   = wid >> 2;
    const int bm   = blockIdx.y * 128;
    const int bn   = blockIdx.x * 128;

    const uint32_t s_a0 = smem_u32(As[0]);
    const uint32_t s_b0 = smem_u32(Bs[0]);

    auto load_chunk = [&](int c, int buf) {
        uint32_t abase = s_a0 + buf * 8192;
        #pragma unroll
        for (int r = 0; r < 2; r++) {
            int s = tid + r * 256;
            int row = s >> 2, seg = s & 3;
            cp_async16(abase + row * 64 + ((seg ^ ((row >> 1) & 3)) << 4),
                       A + (size_t)(bm + row) * K + c * 32 + seg * 8);
        }
        uint32_t bbase = s_b0 + buf * 8192;
        #pragma unroll
        for (int r = 0; r < 2; r++) {
            int s = tid + r * 256;
            int row = s >> 4, seg = s & 15;
            cp_async16(bbase + row * 256 + ((seg ^ (row & 7)) << 4),
                       Bw + (size_t)(c * 32 + row) * N + bn + seg * 8);
        }
    };

    float d[2][8][4];
    #pragma unroll
    for (int mi = 0; mi < 2; mi++)
        #pragma unroll
        for (int ni = 0; ni < 8; ni++)
            #pragma unroll
            for (int r = 0; r < 4; r++) d[mi][ni][r] = 0.0f;

    load_chunk(0, 0); cp_commit();
    load_chunk(1, 1); cp_commit();

    const int lrow = lane & 15;
    const int lseg = lane >> 4;
    const int NCH = K / 32;

    for (int c = 0; c < NCH; c++) {
        if (c == NCH - 1) cp_wait<0>(); else cp_wait<1>();
        __syncthreads();    // chunk c visible; buffer (c+2)%3 free (read at c-1)
        if (c + 2 < NCH) { load_chunk(c + 2, (c + 2) % 3); cp_commit(); }
        uint32_t abase = s_a0 + (c % 3) * 8192;
        uint32_t bbase = s_b0 + (c % 3) * 8192;
        #pragma unroll
        for (int ks = 0; ks < 2; ks++) {
            uint32_t a[2][4];
            #pragma unroll
            for (int mi = 0; mi < 2; mi++) {
                int row = wm * 32 + mi * 16 + lrow;
                int seg = ks * 2 + lseg;
                ldm_x4(a[mi], abase + row * 64 + ((seg ^ ((row >> 1) & 3)) << 4));
            }
            uint32_t b[4][4];
            #pragma unroll
            for (int bp = 0; bp < 4; bp++) {
                int row = ks * 16 + lrow;
                int seg = wn * 8 + bp * 2 + lseg;
                ldm_x4_t(b[bp], bbase + row * 256 + ((seg ^ (row & 7)) << 4));
            }
            #pragma unroll
            for (int mi = 0; mi < 2; mi++)
                #pragma unroll
                for (int ni = 0; ni < 8; ni++)
                    mma16816(d[mi][ni], a[mi], b[ni >> 1][(ni & 1) * 2], b[ni >> 1][(ni & 1) * 2 + 1]);
        }
    }

    const int l4 = lane >> 2, lm = lane & 3;
    float2 bs[8];
    #pragma unroll
    for (int ni = 0; ni < 8; ni++)
        bs[ni] = *(const float2*)(bias + bn + wn * 64 + ni * 8 + lm * 2);

    #pragma unroll
    for (int mi = 0; mi < 2; mi++) {
        #pragma unroll
        for (int half = 0; half < 2; half++) {
            int row = bm + wm * 32 + mi * 16 + half * 8 + l4;
            if (EPI == 2) {
                __nv_bfloat16* C = (__nv_bfloat16*)Cout;
                #pragma unroll
                for (int ni = 0; ni < 8; ni++) {
                    int col = bn + wn * 64 + ni * 8 + lm * 2;
                    float v0 = gelu_fast(d[mi][ni][half * 2 + 0] + bs[ni].x);
                    float v1 = gelu_fast(d[mi][ni][half * 2 + 1] + bs[ni].y);
                    st_cs_u32(C + (size_t)row * N + col, pack_bf16(v0, v1));
                }
            } else {
                float* C = (float*)Cout;
                #pragma unroll
                for (int ni = 0; ni < 8; ni++) {
                    int col = bn + wn * 64 + ni * 8 + lm * 2;
                    float2 res = *(const float2*)(extra + (size_t)row * 128 + col);
                    float2 v;
                    v.x = d[mi][ni][half * 2 + 0] + bs[ni].x + res.x;
                    v.y = d[mi][ni][half * 2 + 1] + bs[ni].y + res.y;
                    st_cs_f2(C + (size_t)row * 128 + col, v);
                }
            }
        }
    }
}

// ---------------- launch ----------------
extern "C" void kernel_launch(void* const* d_in, const int* in_sizes, int n_in,
                              void* d_out, int out_size) {
    const float* x      = (const float*)d_in[0];
    const float* gamma1 = (const float*)d_in[1];
    const float* beta1  = (const float*)d_in[2];
    const float* qkv_w  = (const float*)d_in[3];
    const float* qkv_b  = (const float*)d_in[4];
    const float* proj_w = (const float*)d_in[5];
    const float* proj_b = (const float*)d_in[6];
    const float* rpb    = (const float*)d_in[7];
    const float* gamma2 = (const float*)d_in[8];
    const float* beta2  = (const float*)d_in[9];
    const float* w1     = (const float*)d_in[10];
    const float* b1     = (const float*)d_in[11];
    const float* w2     = (const float*)d_in[12];
    const float* b2     = (const float*)d_in[13];
    float* out = (float*)d_out;

    __nv_bfloat16 *att, *h2, *m1, *wq, *wp, *w1b, *w2b;
    float *y1;
    cudaGetSymbolAddress((void**)&att, g_att);
    cudaGetSymbolAddress((void**)&y1,  g_y1);
    cudaGetSymbolAddress((void**)&h2,  g_h2);
    cudaGetSymbolAddress((void**)&m1,  g_m1);
    cudaGetSymbolAddress((void**)&wq,  g_wq);
    cudaGetSymbolAddress((void**)&wp,  g_wp);
    cudaGetSymbolAddress((void**)&w1b, g_w1b);
    cudaGetSymbolAddress((void**)&w2b, g_w2b);

    cudaFuncSetAttribute(fused_qkv_attn, cudaFuncAttributeMaxDynamicSharedMemorySize, FQ_SMEM);

    convw_kernel<<<49152 / 256, 256>>>(qkv_w, wq, proj_w, wp, w1, w1b, w2, w2b);

    // 1. fused LN1 + qkv GEMM + window attention
    fused_qkv_attn<<<TOK / 128, 256, FQ_SMEM>>>(x, gamma1, beta1, wq, qkv_b, rpb, att);
    // 2. proj GEMM + window reverse + residual -> y1 fp32, fused LN2 -> h2 bf16
    proj_gemm<<<TOK / 128, 256>>>(att, wp, proj_b, x, y1, gamma2, beta2, h2);
    // 3. fc1 + GELU -> m1 bf16   [T,128]@[128,512]
    fc_gemm<2, 128, 512><<<dim3(4, TOK / 128), 256>>>(h2, w1b, b1, nullptr, m1);
    // 4. fc2 + residual -> out   [T,512]@[512,128]
    fc_gemm<3, 512, 128><<<dim3(1, TOK / 128), 256>>>(m1, w2b, b2, y1, out);
}